// round 17
// baseline (speedup 1.0000x reference)
#include <cuda_runtime.h>
#include <cuda_fp16.h>
#include <math.h>
#include <stdint.h>

// Problem constants
#define BB 4
#define SS 4096
#define DD 128
#define HH 8
#define KK 128
#define MM 256

#define BS   (BB*SS)        // 16384
#define BSH  (BB*SS*HH)     // 131072
#define HK   (HH*KK)        // 1024
#define HM   (HH*MM)        // 2048

typedef __half hf;

// -------- scratch (static device globals) --------
__device__ float g_Xn  [BS*DD];
__device__ float g_part[8388608];              // kv split partials: 256 z * 32768
__device__ float g_ksp [32*8*256];             // ksum split partials
__device__ float g_ks  [BB*HH*MM];

// fp16 buffers
__device__ hf b_Q   [BS*DD];
__device__ hf b_Xn  [BS*DD];
__device__ hf b_WqT [HK*DD];
__device__ hf b_WkT [HK*DD];
__device__ hf b_WvT [HK*DD];
__device__ hf b_WoT [DD*HK];
__device__ hf b_proj[MM*KK];
__device__ hf b_fw0T[DD*DD];
__device__ hf b_fw1T[DD*DD];
__device__ hf b_q   [BS*HK];
__device__ hf b_k   [BS*HK];
__device__ hf b_vT  [BS*HK];              // [b,h,k,s]
__device__ hf b_kvT [BB*HH*KK*MM];        // [b,h,k,m]
__device__ hf b_attn[(size_t)BS*HK];      // [b,s,h,k]
__device__ hf b_tA  [BS*DD];
__device__ hf b_tB  [BS*DD];

// ================= asm helpers =================
__device__ __forceinline__ uint32_t smem_u32(const void* p) {
    uint32_t a;
    asm("{ .reg .u64 t; cvta.to.shared.u64 t, %1; cvt.u32.u64 %0, t; }" : "=r"(a) : "l"(p));
    return a;
}
#define CP_ASYNC16(dst, src) asm volatile("cp.async.cg.shared.global [%0], [%1], 16;" :: "r"(dst), "l"(__cvta_generic_to_global(src)))
#define CP_COMMIT()          asm volatile("cp.async.commit_group;")
#define CP_WAIT(n)           asm volatile("cp.async.wait_group %0;" :: "n"(n))

__device__ __forceinline__ void ldsm4(uint32_t* r, uint32_t a) {
    asm volatile("ldmatrix.sync.aligned.m8n8.x4.shared.b16 {%0,%1,%2,%3}, [%4];"
        : "=r"(r[0]), "=r"(r[1]), "=r"(r[2]), "=r"(r[3]) : "r"(a));
}
__device__ __forceinline__ void mma_f16(float* d, const uint32_t* a, const uint32_t* b) {
    asm volatile("mma.sync.aligned.m16n8k16.row.col.f32.f16.f16.f32 "
        "{%0,%1,%2,%3}, {%4,%5,%6,%7}, {%8,%9}, {%0,%1,%2,%3};"
        : "+f"(d[0]), "+f"(d[1]), "+f"(d[2]), "+f"(d[3])
        : "r"(a[0]), "r"(a[1]), "r"(a[2]), "r"(a[3]), "r"(b[0]), "r"(b[1]));
}
__device__ __forceinline__ void st_h2(hf* p, float a, float b) {
    *reinterpret_cast<__half2*>(p) = __halves2half2(__float2half(a), __float2half(b));
}

// ---------------- chunk-tile loader ----------------
template<int R, int NTHR>
__device__ __forceinline__ void load_ct(uint32_t sU,
    const hf* __restrict__ G, int ld, int base0, int k0, int tid)
{
    #pragma unroll
    for (int i = 0; i < (R*8)/NTHR; i++) {
        int idx = tid + i*NTHR;
        int r = idx >> 3, c16 = idx & 7;
        const hf* src = G + (size_t)(base0 + r)*ld + k0 + c16*8;
        int off = r*128 + c16*16;
        int sw = off ^ ((off >> 3) & 0x70);
        CP_ASYNC16(sU + sw, src);
    }
}

// ================= fp16 warp-MMA GEMM (512 thr, 3-stage) =================
// EPI 0: (acc + bias[col]) * alpha
// EPI 6: acc + bias[h*128+row]
// EPI 7: fused Wo: LN(LN(resid + (acc+bias)*mask[row]))
// EPI 8: fused FFN1: LN(elu(acc+bias))
template<int EPI, int NSPLIT, bool OUTB>
__global__ void __launch_bounds__(512) tgemm(
    const hf* __restrict__ Ah, const hf* __restrict__ Bh,
    float* __restrict__ C, hf* __restrict__ Ch,
    const float* __restrict__ bias, const int* __restrict__ mask,
    const float* __restrict__ resid,
    const float* __restrict__ lnAg, const float* __restrict__ lnAb,
    const float* __restrict__ lnBg, const float* __restrict__ lnBb,
    float alpha,
    int Kd, int lda, int ldb, int ldc,
    long long sAb, long long sAh2, long long sBb, long long sBh2,
    long long sCb, long long sCh2, long long sCs)
{
    extern __shared__ char dyn[];
    const int ASZ = 128*128;
    const int BUFSZ = 2*ASZ;

    uint32_t dynU = smem_u32(dyn);
    uint32_t smU = (dynU + 1023u) & ~1023u;

    int tid = threadIdx.x;
    int lane = tid & 31, wid = tid >> 5;
    int wm = (wid & 3) * 32, wn = (wid >> 2) * 32;

    int z = blockIdx.z;
    int split = z % NSPLIT, bh = z / NSPLIT;
    int b = bh >> 3, h = bh & 7;
    Ah += (long long)b*sAb + (long long)h*sAh2;
    Bh += (long long)b*sBb + (long long)h*sBh2;
    long long coff = (long long)b*sCb + (long long)h*sCh2 + (long long)split*sCs;
    if (OUTB) { Ch += coff; } else { C += coff; }
    int kchunk = Kd / NSPLIT;
    int kbeg = split * kchunk;
    int nk = kchunk / 64;
    int m0 = blockIdx.y * 128, n0 = blockIdx.x * 128;

    float acc[2][4][4] = {};

    auto copy_stage = [&](int st, int k0) {
        uint32_t dU = smU + st*BUFSZ;
        load_ct<128,512>(dU,       Ah, lda, m0, k0, tid);
        load_ct<128,512>(dU + ASZ, Bh, ldb, n0, k0, tid);
    };

    copy_stage(0, kbeg);            CP_COMMIT();
    copy_stage(1, kbeg + 64);       CP_COMMIT();

    int rA = wm + (lane & 15);
    int cA = lane >> 4;
    int rB = wn + (lane & 7) + ((lane >> 4) & 1) * 8;
    int cB = (lane >> 3) & 1;

    for (int it = 0; it < nk; it++) {
        if (it < nk - 1) { CP_WAIT(1); } else { CP_WAIT(0); }
        __syncthreads();
        if (it + 2 < nk) {
            copy_stage((it + 2) % 3, kbeg + (it+2)*64);
            CP_COMMIT();
        }
        uint32_t aH = smU + (it % 3)*BUFSZ;
        uint32_t bH = aH + ASZ;
        #pragma unroll
        for (int ks = 0; ks < 4; ks++) {
            uint32_t afh[2][4], bfh[4][2];
            #pragma unroll
            for (int mi = 0; mi < 2; mi++) {
                int row = rA + mi*16;
                int sw = row*128 + (((ks*2 + cA) ^ (row & 7)) * 16);
                ldsm4(afh[mi], aH + sw);
            }
            #pragma unroll
            for (int nj = 0; nj < 2; nj++) {
                int row = rB + nj*16;
                int sw = row*128 + (((ks*2 + cB) ^ (row & 7)) * 16);
                ldsm4(&bfh[nj*2][0], bH + sw);
            }
            #pragma unroll
            for (int mi = 0; mi < 2; mi++)
                #pragma unroll
                for (int ni = 0; ni < 4; ni++)
                    mma_f16(acc[mi][ni], afh[mi], bfh[ni]);
        }
        __syncthreads();
    }

    if (EPI == 7 || EPI == 8) {
        float* smf = reinterpret_cast<float*>(dyn + (smU - dynU));
        #pragma unroll
        for (int mi = 0; mi < 2; mi++) {
            int r0l = wm + mi*16 + (lane >> 2);
            int r1l = r0l + 8;
            int r0g = m0 + r0l, r1g = m0 + r1l;
            float mk0 = 1.0f, mk1 = 1.0f;
            if (EPI == 7) { mk0 = (float)mask[r0g]; mk1 = (float)mask[r1g]; }
            #pragma unroll
            for (int ni = 0; ni < 4; ni++) {
                int c0 = wn + ni*8 + (lane & 3)*2;
                float d0 = acc[mi][ni][0] + bias[c0];
                float d1 = acc[mi][ni][1] + bias[c0+1];
                float d2 = acc[mi][ni][2] + bias[c0];
                float d3 = acc[mi][ni][3] + bias[c0+1];
                if (EPI == 7) {
                    d0 = resid[(size_t)r0g*DD + c0]     + d0*mk0;
                    d1 = resid[(size_t)r0g*DD + c0 + 1] + d1*mk0;
                    d2 = resid[(size_t)r1g*DD + c0]     + d2*mk1;
                    d3 = resid[(size_t)r1g*DD + c0 + 1] + d3*mk1;
                } else {
                    d0 = d0 > 0.0f ? d0 : expm1f(d0);
                    d1 = d1 > 0.0f ? d1 : expm1f(d1);
                    d2 = d2 > 0.0f ? d2 : expm1f(d2);
                    d3 = d3 > 0.0f ? d3 : expm1f(d3);
                }
                smf[r0l*132 + c0] = d0; smf[r0l*132 + c0+1] = d1;
                smf[r1l*132 + c0] = d2; smf[r1l*132 + c0+1] = d3;
            }
        }
        __syncthreads();
        int row = tid >> 2, sub = tid & 3;
        float* rp = smf + row*132 + sub*32;
        float s = 0.0f;
        #pragma unroll
        for (int j = 0; j < 32; j++) s += rp[j];
        s += __shfl_xor_sync(0xffffffffu, s, 1);
        s += __shfl_xor_sync(0xffffffffu, s, 2);
        float mu = s * (1.0f/128.0f);
        float s2 = 0.0f;
        #pragma unroll
        for (int j = 0; j < 32; j++) { float d = rp[j] - mu; s2 += d*d; }
        s2 += __shfl_xor_sync(0xffffffffu, s2, 1);
        s2 += __shfl_xor_sync(0xffffffffu, s2, 2);
        float rs = rsqrtf(s2 * (1.0f/128.0f) + 1e-3f);
        if (EPI == 8) {
            #pragma unroll
            for (int j = 0; j < 32; j += 2) {
                int c = sub*32 + j;
                float y0 = (rp[j]   - mu)*rs*lnAg[c]   + lnAb[c];
                float y1 = (rp[j+1] - mu)*rs*lnAg[c+1] + lnAb[c+1];
                st_h2(Ch + (size_t)(m0 + row)*DD + c, y0, y1);
            }
        } else {
            float t = 0.0f;
            #pragma unroll
            for (int j = 0; j < 32; j++) {
                int c = sub*32 + j;
                float y = (rp[j] - mu)*rs*lnAg[c] + lnAb[c];
                rp[j] = y; t += y;
            }
            t += __shfl_xor_sync(0xffffffffu, t, 1);
            t += __shfl_xor_sync(0xffffffffu, t, 2);
            float mu2 = t * (1.0f/128.0f);
            float v2 = 0.0f;
            #pragma unroll
            for (int j = 0; j < 32; j++) { float d = rp[j] - mu2; v2 += d*d; }
            v2 += __shfl_xor_sync(0xffffffffu, v2, 1);
            v2 += __shfl_xor_sync(0xffffffffu, v2, 2);
            float rs2 = rsqrtf(v2 * (1.0f/128.0f) + 1e-3f);
            #pragma unroll
            for (int j = 0; j < 32; j += 2) {
                int c = sub*32 + j;
                float y0 = (rp[j]   - mu2)*rs2*lnBg[c]   + lnBb[c];
                float y1 = (rp[j+1] - mu2)*rs2*lnBg[c+1] + lnBb[c+1];
                st_h2(Ch + (size_t)(m0 + row)*DD + c, y0, y1);
            }
        }
        return;
    }

    #pragma unroll
    for (int mi = 0; mi < 2; mi++) {
        int r0 = m0 + wm + mi*16 + (lane >> 2);
        int r1 = r0 + 8;
        float f0 = 1.0f, f1 = 1.0f;
        if (EPI == 6) {
            f0 = bias[(h << 7) + r0];
            f1 = bias[(h << 7) + r1];
        }
        #pragma unroll
        for (int ni = 0; ni < 4; ni++) {
            int c0 = n0 + wn + ni*8 + (lane & 3)*2;
            float d0 = acc[mi][ni][0], d1 = acc[mi][ni][1];
            float d2 = acc[mi][ni][2], d3 = acc[mi][ni][3];
            if (EPI == 0) {
                float b0 = bias ? bias[c0] : 0.0f, b1 = bias ? bias[c0+1] : 0.0f;
                d0 = (d0 + b0)*alpha; d1 = (d1 + b1)*alpha;
                d2 = (d2 + b0)*alpha; d3 = (d3 + b1)*alpha;
            } else if (EPI == 6) {
                d0 += f0; d1 += f0; d2 += f1; d3 += f1;
            }
            if (OUTB) {
                st_h2(Ch + (size_t)r0*ldc + c0, d0, d1);
                st_h2(Ch + (size_t)r1*ldc + c0, d2, d3);
            } else {
                *reinterpret_cast<float2*>(C + (size_t)r0*ldc + c0) = make_float2(d0, d1);
                *reinterpret_cast<float2*>(C + (size_t)r1*ldc + c0) = make_float2(d2, d3);
            }
        }
    }
}

// ================= fused kp+kv+ksum kernel (512 threads) =================
// Per (bh, mh, split): for each 128-token chunk (4 per split):
//   phase A: kp[m128, s128] = (elu(proj@k^T)+1)/sqrt(M)*mask -> smem fp16
//   phase B: kv_acc[m128, k128] += kp @ vT^T
// Prefetch issued at END of body after __syncthreads (2-buffer, distance-2 safe).
#define FK_PJ   0        // proj tile: 2 chunks x 16KB
#define FK_KP   32768    // kp tile:   2 chunks x 16KB
#define FK_BB   65536    // B pipeline: 2 x 16KB
#define FK_KS   98304    // ksum smem: 128*16*4 = 8KB
#define SMEM_FKV (106496 + 1024)

__global__ void __launch_bounds__(512) fkv_kernel(
    const hf* __restrict__ kh, const hf* __restrict__ projh,
    const hf* __restrict__ vTh, const int* __restrict__ mask,
    float* __restrict__ part, float* __restrict__ ksp)
{
    extern __shared__ char dyn[];
    uint32_t dynU = smem_u32(dyn);
    uint32_t smU = (dynU + 1023u) & ~1023u;
    char* base = dyn + (smU - dynU);

    int tid = threadIdx.x, lane = tid & 31, wid = tid >> 5;
    int wm = (wid & 3) * 32, wn = (wid >> 2) * 32;

    int z = blockIdx.z;             // bh*8 + split
    int split = z & 7, bh = z >> 3;
    int b = bh >> 3, h = bh & 7;
    int mh = blockIdx.y;            // 0/1 -> m half
    int sbase = split * 512;

    const hf* kp_ = kh + ((size_t)(b*SS + sbase))*HK + h*KK;
    const hf* vp_ = vTh + (size_t)bh*KK*SS;
    const float inv_sqrt_m = 0.0625f;
    const int* mrow = mask + b*SS + sbase;

    auto loadB = [&](int it) {
        uint32_t dU = smU + FK_BB + (it & 1)*16384;
        int chunk = it >> 2, g = it & 3;
        if (g < 2) load_ct<128,512>(dU, kp_, HK, chunk*128, g*64, tid);
        else       load_ct<128,512>(dU, vp_, SS, 0, sbase + chunk*128 + (g-2)*64, tid);
    };

    load_ct<128,512>(smU + FK_PJ,         projh, KK, mh*128, 0,  tid);
    load_ct<128,512>(smU + FK_PJ + 16384, projh, KK, mh*128, 64, tid);
    loadB(0); CP_COMMIT();
    loadB(1); CP_COMMIT();

    int rA = wm + (lane & 15);
    int cA = lane >> 4;
    int rB = wn + (lane & 7) + ((lane >> 4) & 1) * 8;
    int cB = (lane >> 3) & 1;

    float accA[2][4][4] = {};
    float accKV[2][4][4] = {};
    float rsum[2][2] = {};

    for (int it = 0; it < 16; it++) {
        if (it < 15) { CP_WAIT(1); } else { CP_WAIT(0); }
        __syncthreads();

        int g = it & 3;
        uint32_t aU = (g < 2) ? (smU + FK_PJ + g*16384)
                              : (smU + FK_KP + (g - 2)*16384);
        uint32_t bU = smU + FK_BB + (it & 1)*16384;
        float (*acc)[4][4] = (g < 2) ? accA : accKV;

        #pragma unroll
        for (int ks = 0; ks < 4; ks++) {
            uint32_t afh[2][4], bfh[4][2];
            #pragma unroll
            for (int mi = 0; mi < 2; mi++) {
                int row = rA + mi*16;
                int sw = row*128 + (((ks*2 + cA) ^ (row & 7)) * 16);
                ldsm4(afh[mi], aU + sw);
            }
            #pragma unroll
            for (int nj = 0; nj < 2; nj++) {
                int row = rB + nj*16;
                int sw = row*128 + (((ks*2 + cB) ^ (row & 7)) * 16);
                ldsm4(&bfh[nj*2][0], bU + sw);
            }
            #pragma unroll
            for (int mi = 0; mi < 2; mi++)
                #pragma unroll
                for (int ni = 0; ni < 4; ni++)
                    mma_f16(acc[mi][ni], afh[mi], bfh[ni]);
        }

        if (g == 1) {
            int chunk = it >> 2;
            #pragma unroll
            for (int mi = 0; mi < 2; mi++) {
                int r0 = wm + mi*16 + (lane >> 2);
                int r1 = r0 + 8;
                #pragma unroll
                for (int ni = 0; ni < 4; ni++) {
                    int c = wn + ni*8 + (lane & 3)*2;
                    float m0f = (float)mrow[chunk*128 + c];
                    float m1f = (float)mrow[chunk*128 + c + 1];
                    float d0 = accA[mi][ni][0], d1 = accA[mi][ni][1];
                    float d2 = accA[mi][ni][2], d3 = accA[mi][ni][3];
                    d0 = (d0 > 0.0f ? d0 + 1.0f : expf(d0)) * inv_sqrt_m * m0f;
                    d1 = (d1 > 0.0f ? d1 + 1.0f : expf(d1)) * inv_sqrt_m * m1f;
                    d2 = (d2 > 0.0f ? d2 + 1.0f : expf(d2)) * inv_sqrt_m * m0f;
                    d3 = (d3 > 0.0f ? d3 + 1.0f : expf(d3)) * inv_sqrt_m * m1f;
                    rsum[mi][0] += d0 + d1;
                    rsum[mi][1] += d2 + d3;
                    int ch2 = c >> 6, cin = c & 63;
                    int o0 = r0*128 + cin*2;  int sw0 = o0 ^ ((o0 >> 3) & 0x70);
                    int o1 = r1*128 + cin*2;  int sw1 = o1 ^ ((o1 >> 3) & 0x70);
                    st_h2(reinterpret_cast<hf*>(base + FK_KP + ch2*16384 + sw0), d0, d1);
                    st_h2(reinterpret_cast<hf*>(base + FK_KP + ch2*16384 + sw1), d2, d3);
                }
            }
            #pragma unroll
            for (int mi = 0; mi < 2; mi++)
                #pragma unroll
                for (int ni = 0; ni < 4; ni++)
                    #pragma unroll
                    for (int c = 0; c < 4; c++)
                        accA[mi][ni][c] = 0.0f;
        }

        __syncthreads();   // B-buffer reads done + kp smem visible

        if (it + 2 < 16) { loadB(it + 2); CP_COMMIT(); }
    }

    // kv partial out
    float* po = part + (size_t)z*32768 + (size_t)mh*128*128;
    #pragma unroll
    for (int mi = 0; mi < 2; mi++) {
        int r0 = wm + mi*16 + (lane >> 2);
        int r1 = r0 + 8;
        #pragma unroll
        for (int ni = 0; ni < 4; ni++) {
            int c0 = wn + ni*8 + (lane & 3)*2;
            *reinterpret_cast<float2*>(po + r0*128 + c0) = make_float2(accKV[mi][ni][0], accKV[mi][ni][1]);
            *reinterpret_cast<float2*>(po + r1*128 + c0) = make_float2(accKV[mi][ni][2], accKV[mi][ni][3]);
        }
    }

    // ksum: deterministic smem reduce -> split partial
    float* ksm = reinterpret_cast<float*>(base + FK_KS);
    int slot = (wid >> 2)*4 + (lane & 3);
    #pragma unroll
    for (int mi = 0; mi < 2; mi++) {
        int r0 = wm + mi*16 + (lane >> 2);
        ksm[r0*16 + slot]       = rsum[mi][0];
        ksm[(r0 + 8)*16 + slot] = rsum[mi][1];
    }
    __syncthreads();
    if (tid < 128) {
        float s = 0.0f;
        #pragma unroll
        for (int j = 0; j < 16; j++) s += ksm[tid*16 + j];
        ksp[(size_t)z*256 + mh*128 + tid] = s;
    }
}

// ---------------- ksum split reduce ----------------
__global__ void ksum_reduce8_kernel(const float* __restrict__ ksp, float* __restrict__ ks)
{
    int bh = blockIdx.x, m = threadIdx.x;
    float s = 0.0f;
    #pragma unroll
    for (int sp = 0; sp < 8; sp++) s += ksp[(size_t)(bh*8 + sp)*256 + m];
    ks[bh*256 + m] = s;
}

// ================= fused qp + denom + attn kernel (256 threads) =================
#define FA_QP   0
#define FA_QT   32768
#define FA_BBUF 49152
#define SMEM_FATTN (81920 + 1024)

__global__ void __launch_bounds__(256) fattn_kernel(
    const hf* __restrict__ qh,
    const hf* __restrict__ projh,
    const hf* __restrict__ kvh,
    const float* __restrict__ ksum,
    hf* __restrict__ outh)
{
    extern __shared__ char dyn[];
    __shared__ float dn_smem[64];
    uint32_t dynU = smem_u32(dyn);
    uint32_t smU = (dynU + 1023u) & ~1023u;

    int tid = threadIdx.x;
    int lane = tid & 31, wid = tid >> 5;
    int ws = wid & 1, wn = wid >> 1;

    int bh = blockIdx.z;
    int b = bh >> 3, h = bh & 7;
    int s0 = blockIdx.y * 64;

    const hf* qhp = qh + ((size_t)(b*SS + s0))*HK + h*KK;
    const hf* kvhp = kvh + (size_t)bh*KK*MM;
    const float* ksp2 = ksum + bh*MM;

    const float inv_sqrt_m = 0.0625f;

    load_ct<64,256>(smU + FA_QT,        qhp, HK, 0, 0,  tid);
    load_ct<64,256>(smU + FA_QT + 8192, qhp, HK, 0, 64, tid);

    auto loadB = [&](int it) {
        uint32_t dU = smU + FA_BBUF + (it & 1)*16384;
        if (it < 4) {
            int mh = it >> 1, kt = it & 1;
            load_ct<128,256>(dU, projh, KK, mh*128, kt*64, tid);
        } else {
            int ch = it - 4;
            load_ct<128,256>(dU, kvhp, MM, 0, ch*64, tid);
        }
    };

    loadB(0); CP_COMMIT();
    loadB(1); CP_COMMIT();

    int rAl = ws*32 + (lane & 15);
    int cA  = lane >> 4;
    int rBl = wn*32 + (lane & 7) + ((lane >> 4) & 1) * 8;
    int cB  = (lane >> 3) & 1;

    float acc[2][4][4] = {};

    for (int it = 0; it < 8; it++) {
        if (it < 7) { CP_WAIT(1); } else { CP_WAIT(0); }
        __syncthreads();

        uint32_t aH;
        if (it < 4) {
            int kt = it & 1;
            aH = smU + FA_QT + kt*8192;
        } else {
            int ch = it - 4;
            aH = smU + FA_QP + ch*8192;
        }
        uint32_t bH = smU + FA_BBUF + (it & 1)*16384;

        #pragma unroll
        for (int ks = 0; ks < 4; ks++) {
            uint32_t afh[2][4], bfh[4][2];
            #pragma unroll
            for (int mi = 0; mi < 2; mi++) {
                int row = rAl + mi*16;
                int sw = row*128 + (((ks*2 + cA) ^ (row & 7)) * 16);
                ldsm4(afh[mi], aH + sw);
            }
            #pragma unroll
            for (int nj = 0; nj < 2; nj++) {
                int row = rBl + nj*16;
                int sw = row*128 + (((ks*2 + cB) ^ (row & 7)) * 16);
                ldsm4(&bfh[nj*2][0], bH + sw);
            }
            #pragma unroll
            for (int mi = 0; mi < 2; mi++)
                #pragma unroll
                for (int ni = 0; ni < 4; ni++)
                    mma_f16(acc[mi][ni], afh[mi], bfh[ni]);
        }

        if (it == 1 || it == 3) {
            int mh = it >> 1;
            char* base = dyn + (smU - dynU);
            #pragma unroll
            for (int mi = 0; mi < 2; mi++) {
                int r0 = ws*32 + mi*16 + (lane >> 2);
                int r1 = r0 + 8;
                #pragma unroll
                for (int ni = 0; ni < 4; ni++) {
                    int cl = wn*32 + ni*8 + (lane & 3)*2;
                    int mg = mh*128 + cl;
                    int chunk = mg >> 6, cin = mg & 63;
                    float d0 = acc[mi][ni][0], d1 = acc[mi][ni][1];
                    float d2 = acc[mi][ni][2], d3 = acc[mi][ni][3];
                    d0 = (d0 > 0.0f ? d0 + 1.0f : expf(d0)) * inv_sqrt_m;
                    d1 = (d1 > 0.0f ? d1 + 1.0f : expf(d1)) * inv_sqrt_m;
                    d2 = (d2 > 0.0f ? d2 + 1.0f : expf(d2)) * inv_sqrt_m;
                    d3 = (d3 > 0.0f ? d3 + 1.0f : expf(d3)) * inv_sqrt_m;
                    int o0 = r0*128 + cin*2;  int sw0 = o0 ^ ((o0 >> 3) & 0x70);
                    int o1 = r1*128 + cin*2;  int sw1 = o1 ^ ((o1 >> 3) & 0x70);
                    st_h2(reinterpret_cast<hf*>(base + FA_QP + chunk*8192 + sw0), d0, d1);
                    st_h2(reinterpret_cast<hf*>(base + FA_QP + chunk*8192 + sw1), d2, d3);
                }
            }
            #pragma unroll
            for (int mi = 0; mi < 2; mi++)
                #pragma unroll
                for (int ni = 0; ni < 4; ni++)
                    #pragma unroll
                    for (int c = 0; c < 4; c++)
                        acc[mi][ni][c] = 0.0f;
        }

        __syncthreads();

        if (it == 3) {
            int row = tid >> 2, part2 = tid & 3;
            char* base = dyn + (smU - dynU);
            float s = 0.0f;
            for (int j = 0; j < 64; j++) {
                int o = row*128 + j*2;
                int sw = o ^ ((o >> 3) & 0x70);
                float hv = __half2float(*reinterpret_cast<hf*>(base + FA_QP + part2*8192 + sw));
                s += hv * ksp2[part2*64 + j];
            }
            s += __shfl_down_sync(0xffffffffu, s, 1);
            s += __shfl_down_sync(0xffffffffu, s, 2);
            if (part2 == 0) dn_smem[row] = 1.0f / (s + 1e-6f);
            __syncthreads();
        }

        if (it + 2 < 8) { loadB(it + 2); CP_COMMIT(); }
    }

    #pragma unroll
    for (int mi = 0; mi < 2; mi++) {
        int r0 = ws*32 + mi*16 + (lane >> 2);
        int r1 = r0 + 8;
        float f0 = dn_smem[r0], f1 = dn_smem[r1];
        #pragma unroll
        for (int ni = 0; ni < 4; ni++) {
            int ck = wn*32 + ni*8 + (lane & 3)*2;
            size_t a0 = ((size_t)(b*SS + s0 + r0))*HK + h*KK + ck;
            size_t a1 = ((size_t)(b*SS + s0 + r1))*HK + h*KK + ck;
            st_h2(outh + a0, acc[mi][ni][0]*f0, acc[mi][ni][1]*f0);
            st_h2(outh + a1, acc[mi][ni][2]*f1, acc[mi][ni][3]*f1);
        }
    }
}

// ---------------- converts ----------------
__global__ void conv_kernel(const float* __restrict__ src, hf* __restrict__ hi, int n)
{
    int i = blockIdx.x*256 + threadIdx.x;
    if (i < n) hi[i] = __float2half(src[i]);
}
__global__ void convT3_kernel(const float* __restrict__ s0, const float* __restrict__ s1,
                              const float* __restrict__ s2,
                              hf* __restrict__ h0, hf* __restrict__ h1, hf* __restrict__ h2,
                              int R, int C)
{
    const float* src = blockIdx.y == 0 ? s0 : (blockIdx.y == 1 ? s1 : s2);
    hf* hi = blockIdx.y == 0 ? h0 : (blockIdx.y == 1 ? h1 : h2);
    if (src == nullptr) return;
    int i = blockIdx.x*256 + threadIdx.x;
    if (i < R*C) {
        int r = i / C, c = i % C;
        hi[(size_t)c*R + r] = __float2half(src[i]);
    }
}
__global__ void convT_kernel(const float* __restrict__ src, hf* __restrict__ hi, int R, int C)
{
    int i = blockIdx.x*256 + threadIdx.x;
    if (i < R*C) {
        int r = i / C, c = i % C;
        hi[(size_t)c*R + r] = __float2half(src[i]);
    }
}

// ---------------- LayerNorm (Xn only) ----------------
__global__ void ln_kernel(const float* __restrict__ in1,
                          const float* __restrict__ gamma, const float* __restrict__ beta,
                          float* __restrict__ outf, hf* __restrict__ outh)
{
    int row = blockIdx.x;
    int t = threadIdx.x;
    __shared__ float smv[4];
    float x = in1[(size_t)row*DD + t];
    float s = x;
    #pragma unroll
    for (int o = 16; o; o >>= 1) s += __shfl_down_sync(0xffffffffu, s, o);
    if ((t & 31) == 0) smv[t >> 5] = s;
    __syncthreads();
    float mu = (smv[0] + smv[1] + smv[2] + smv[3]) * (1.0f/128.0f);
    float d = x - mu;
    float s2 = d * d;
    __syncthreads();
    #pragma unroll
    for (int o = 16; o; o >>= 1) s2 += __shfl_down_sync(0xffffffffu, s2, o);
    if ((t & 31) == 0) smv[t >> 5] = s2;
    __syncthreads();
    float var = (smv[0] + smv[1] + smv[2] + smv[3]) * (1.0f/128.0f);
    float y = d * rsqrtf(var + 1e-3f) * gamma[t] + beta[t];
    size_t idx = (size_t)row*DD + t;
    if (outf) outf[idx] = y;
    if (outh) outh[idx] = __float2half(y);
}

// ---------------- kv reduce + transpose ----------------
__global__ void reduce_kvT_kernel(const float* __restrict__ part, hf* __restrict__ hi)
{
    int bh = blockIdx.x;
    int tm = (blockIdx.y >> 1) * 64;
    int tk = (blockIdx.y & 1) * 64;
    __shared__ float t[64][65];
    const float* p = part + (size_t)bh*8*32768;
    int tid = threadIdx.x;
    #pragma unroll
    for (int i = 0; i < 16; i++) {
        int idx = tid + i*256;
        int r = idx >> 6, c = idx & 63;
        float s = 0.0f;
        #pragma unroll
        for (int sp = 0; sp < 8; sp++) s += p[sp*32768 + (tm+r)*128 + tk+c];
        t[c][r] = s;
    }
    __syncthreads();
    hf* H = hi + (size_t)bh*KK*MM;
    #pragma unroll
    for (int i = 0; i < 16; i++) {
        int idx = tid + i*256;
        int kk2 = idx >> 6, mm2 = idx & 63;
        H[(size_t)(tk+kk2)*MM + tm+mm2] = __float2half(t[kk2][mm2]);
    }
}

// ---------------- host-side launch ----------------
template<typename T>
static T* sym_addr(const void* sym)
{
    void* p = nullptr;
    cudaGetSymbolAddress(&p, sym);
    return (T*)p;
}

#define SMEM_REQ (3*2*128*128 + 1024)   // 99328

extern "C" void kernel_launch(void* const* d_in, const int* in_sizes, int n_in,
                              void* d_out, int out_size)
{
    (void)in_sizes; (void)n_in; (void)out_size;
    const float* Q      = (const float*)d_in[0];
    const float* X      = (const float*)d_in[1];
    const int*   mask   = (const int*)  d_in[2];
    const float* Wq     = (const float*)d_in[3];
    const float* bq     = (const float*)d_in[4];
    const float* Wk     = (const float*)d_in[5];
    const float* bk     = (const float*)d_in[6];
    const float* Wv     = (const float*)d_in[7];
    const float* bv     = (const float*)d_in[8];
    const float* Wo     = (const float*)d_in[9];
    const float* bo     = (const float*)d_in[10];
    const float* proj   = (const float*)d_in[11];
    const float* ln1_g  = (const float*)d_in[12];
    const float* ln1_b  = (const float*)d_in[13];
    const float* ln2_g  = (const float*)d_in[14];
    const float* ln2_b  = (const float*)d_in[15];
    const float* fln0_g = (const float*)d_in[16];
    const float* fln0_b = (const float*)d_in[17];
    const float* f_w0   = (const float*)d_in[18];
    const float* f_b0   = (const float*)d_in[19];
    const float* fln1_g = (const float*)d_in[20];
    const float* fln1_b = (const float*)d_in[21];
    const float* f_w1   = (const float*)d_in[22];
    const float* f_b1   = (const float*)d_in[23];
    float* out = (float*)d_out;

    float* Xn   = sym_addr<float>(g_Xn);
    float* part = sym_addr<float>(g_part);
    float* ksp  = sym_addr<float>(g_ksp);
    float* ks   = sym_addr<float>(g_ks);

    hf* bQ    = sym_addr<hf>(b_Q);
    hf* bXn   = sym_addr<hf>(b_Xn);
    hf* bWqT  = sym_addr<hf>(b_WqT);
    hf* bWkT  = sym_addr<hf>(b_WkT);
    hf* bWvT  = sym_addr<hf>(b_WvT);
    hf* bWoT  = sym_addr<hf>(b_WoT);
    hf* bproj = sym_addr<hf>(b_proj);
    hf* bfw0T = sym_addr<hf>(b_fw0T);
    hf* bfw1T = sym_addr<hf>(b_fw1T);
    hf* bq_h  = sym_addr<hf>(b_q);
    hf* bk_h  = sym_addr<hf>(b_k);
    hf* bvT_h = sym_addr<hf>(b_vT);
    hf* bkvT_h= sym_addr<hf>(b_kvT);
    hf* bat_h = sym_addr<hf>(b_attn);
    hf* btA_h = sym_addr<hf>(b_tA);
    hf* btB_h = sym_addr<hf>(b_tB);

    const float scale_q = 0.08838834764831845f;  // 1/sqrt(128)

    cudaFuncSetAttribute(tgemm<0,1,true >, cudaFuncAttributeMaxDynamicSharedMemorySize, SMEM_REQ);
    cudaFuncSetAttribute(tgemm<6,1,true >, cudaFuncAttributeMaxDynamicSharedMemorySize, SMEM_REQ);
    cudaFuncSetAttribute(tgemm<7,1,true >, cudaFuncAttributeMaxDynamicSharedMemorySize, SMEM_REQ);
    cudaFuncSetAttribute(tgemm<8,1,true >, cudaFuncAttributeMaxDynamicSharedMemorySize, SMEM_REQ);
    cudaFuncSetAttribute(tgemm<0,1,false>, cudaFuncAttributeMaxDynamicSharedMemorySize, SMEM_REQ);
    cudaFuncSetAttribute(fkv_kernel, cudaFuncAttributeMaxDynamicSharedMemorySize, SMEM_FKV);
    cudaFuncSetAttribute(fattn_kernel, cudaFuncAttributeMaxDynamicSharedMemorySize, SMEM_FATTN);

    // 0. converts
    conv_kernel<<<(BS*DD + 255)/256, 256>>>(Q, bQ, BS*DD);
    conv_kernel<<<(MM*KK + 255)/256, 256>>>(proj, bproj, MM*KK);
    convT3_kernel<<<dim3((DD*HK + 255)/256, 3), 256>>>(
        Wq, Wk, Wv, bWqT, bWkT, bWvT, DD, HK);
    convT_kernel<<<(HK*DD + 255)/256, 256>>>(Wo, bWoT, HK, DD);
    convT3_kernel<<<dim3((DD*DD + 255)/256, 3), 256>>>(
        f_w0, f_w1, nullptr, bfw0T, bfw1T, nullptr, DD, DD);

    // 1. Xn = LN(X; ln1)
    ln_kernel<<<BS, 128>>>(X, ln1_g, ln1_b, Xn, bXn);

    // 2-3. q, k projections -> fp16 [BS, HK]
    tgemm<0,1,true><<<dim3(HK/128, BS/128, 1), 512, SMEM_REQ>>>(
        bQ, bWqT, nullptr, bq_h, bq, nullptr, nullptr, nullptr, nullptr, nullptr, nullptr, scale_q,
        DD, DD, DD, HK, 0,0,0,0, 0,0,0);
    tgemm<0,1,true><<<dim3(HK/128, BS/128, 1), 512, SMEM_REQ>>>(
        bXn, bWkT, nullptr, bk_h, bk, nullptr, nullptr, nullptr, nullptr, nullptr, nullptr, 1.0f,
        DD, DD, DD, HK, 0,0,0,0, 0,0,0);

    // 4. vT[b,h,k,s] = Wv^T(h) @ Xn^T(b) + bv[h,k]
    tgemm<6,1,true><<<dim3(SS/128, 1, 32), 512, SMEM_REQ>>>(
        bWvT, bXn, nullptr, bvT_h, bv, nullptr, nullptr, nullptr, nullptr, nullptr, nullptr, 1.0f,
        DD, DD, DD, SS,
        0, (long long)KK*DD, (long long)SS*DD, 0,
        (long long)HH*KK*SS, (long long)KK*SS, 0);

    // 5. fused kp+kv+ksum
    fkv_kernel<<<dim3(1, 2, 256), 512, SMEM_FKV>>>(
        bk_h, bproj, bvT_h, mask, part, ksp);
    reduce_kvT_kernel<<<dim3(32, 8), 256>>>(part, bkvT_h);
    ksum_reduce8_kernel<<<32, 256>>>(ksp, ks);

    // 6. fused qp + denom + attn
    fattn_kernel<<<dim3(1, SS/64, 32), 256, SMEM_FATTN>>>(
        bq_h, bproj, bkvT_h, ks, bat_h);

    // 7. fused Wo-GEMM + residual + double LN -> tA
    tgemm<7,1,true><<<dim3(1, BS/128, 1), 512, SMEM_REQ>>>(
        bat_h, bWoT, nullptr, btA_h, bo, mask, Xn, ln2_g, ln2_b, fln0_g, fln0_b, 1.0f,
        HK, HK, HK, DD, 0,0,0,0, 0,0,0);

    // 8. fused FFN1-GEMM + elu + LN -> tB
    tgemm<8,1,true><<<dim3(1, BS/128, 1), 512, SMEM_REQ>>>(
        btA_h, bfw0T, nullptr, btB_h, f_b0, nullptr, nullptr, fln1_g, fln1_b, nullptr, nullptr, 1.0f,
        DD, DD, DD, DD, 0,0,0,0, 0,0,0);

    // 9. FFN2 -> out
    tgemm<0,1,false><<<dim3(1, BS/128, 1), 512, SMEM_REQ>>>(
        btB_h, bfw1T, out, nullptr, f_b1, nullptr, nullptr, nullptr, nullptr, nullptr, nullptr, 1.0f,
        DD, DD, DD, DD, 0,0,0,0, 0,0,0);
}